// round 6
// baseline (speedup 1.0000x reference)
#include <cuda_runtime.h>
#include <cuda_bf16.h>

#define NCLS   1000
#define NCLS4  250          // NCLS / 4 float4 per row
#define NBLK   592          // 148 SMs x 4 resident blocks (256 thr, 32 regs)
#define NWARPS (NBLK * 8)   // total persistent warps

// Scratch (no device allocation allowed -> __device__ globals)
__device__ float2 g_part[NBLK];   // per-block (sum_loss, sum_valid)

// ---------------------------------------------------------------------------
// Persistent main pass: warp-per-token with a strided token loop; the fused
// loss/count reduction lives in lane 0 of each warp, combined once per block.
// ---------------------------------------------------------------------------
__global__ __launch_bounds__(256) void hll_main(
    const float* __restrict__ inputs,
    const int*   __restrict__ target,   // int32 (JAX downcasts int64 w/o x64)
    int N)
{
    const int warp  = threadIdx.x >> 5;
    const int lane  = threadIdx.x & 31;
    const int gwarp = (blockIdx.x << 3) + warp;

    float lsum = 0.f, csum = 0.f;       // lane-0 accumulators

    for (int n = gwarp; n < N; n += NWARPS) {
        const int ti = target[n];
        const bool valid = (ti != -100);
        const int t   = valid ? ti : 0;
        const int lo1 = (t / 10)  * 10;    // start of 10-block
        const int lo2 = (t / 100) * 100;   // start of 100-block

        const float*  __restrict__ rowf = inputs + (size_t)n * NCLS;
        const float4* __restrict__ row  = reinterpret_cast<const float4*>(rowf);

        // ---- Streaming pass: full row sum, compare-free ----
        float a0 = 0.f, a1 = 0.f, a2 = 0.f, a3 = 0.f;
        #pragma unroll
        for (int it = 0; it < 8; ++it) {
            const int idx = lane + (it << 5);
            if (idx < NCLS4) {
                const float4 v = row[idx];
                a0 += v.x; a1 += v.y; a2 += v.z; a3 += v.w;
            }
        }
        float s3 = (a0 + a1) + (a2 + a3);

        // ---- Targeted re-reads (L1 hits) ----
        float s2 = 0.f, s1 = 0.f;
        if (lane < 25) {                       // 100 floats = 25 float4
            const float4 v = row[(lo2 >> 2) + lane];
            s2 = (v.x + v.y) + (v.z + v.w);
        }
        if (lane < 10) s1 = rowf[lo1 + lane];  // 10 floats
        const float s0 = rowf[t];              // read by all lanes (broadcast, L1)

        // ---- Warp butterfly reduce s1,s2,s3 (s0 needs no reduce) ----
        #pragma unroll
        for (int off = 16; off; off >>= 1) {
            s1 += __shfl_xor_sync(0xffffffffu, s1, off);
            s2 += __shfl_xor_sync(0xffffffffu, s2, off);
            s3 += __shfl_xor_sync(0xffffffffu, s3, off);
        }

        if (lane == 0 && valid) {
            const float t0 = (s0 != 0.f) ? -logf(s0 / s1) : 0.f;
            const float t1 = (s1 != 0.f) ? -logf(s1 / s2) : 0.f;
            const float t2 = (s2 != 0.f) ? -logf(s2 / s3) : 0.f;
            lsum += t0 + 0.60653065971263342f * t1   // exp(-0.5)
                       + 0.36787944117144233f * t2;  // exp(-1.0)
            csum += 1.f;
        }
    }

    // ---- Per-block combine of the 8 warp accumulators ----
    __shared__ float2 sacc[8];
    if (lane == 0) sacc[warp] = make_float2(lsum, csum);
    __syncthreads();
    if (threadIdx.x == 0) {
        float L = 0.f, C = 0.f;
        #pragma unroll
        for (int w = 0; w < 8; ++w) { L += sacc[w].x; C += sacc[w].y; }
        g_part[blockIdx.x] = make_float2(L, C);
    }
}

// ---------------------------------------------------------------------------
// Single tiny final reduction over NBLK partials (deterministic, no atomics).
// ---------------------------------------------------------------------------
__global__ __launch_bounds__(256) void hll_final(float* __restrict__ out)
{
    float l = 0.f, c = 0.f;
    for (int i = threadIdx.x; i < NBLK; i += 256) {
        const float2 v = g_part[i];
        l += v.x;
        c += v.y;
    }
    #pragma unroll
    for (int off = 16; off; off >>= 1) {
        l += __shfl_xor_sync(0xffffffffu, l, off);
        c += __shfl_xor_sync(0xffffffffu, c, off);
    }
    __shared__ float sl[8], sc[8];
    const int warp = threadIdx.x >> 5;
    const int lane = threadIdx.x & 31;
    if (lane == 0) { sl[warp] = l; sc[warp] = c; }
    __syncthreads();
    if (threadIdx.x == 0) {
        float L = 0.f, C = 0.f;
        #pragma unroll
        for (int w = 0; w < 8; ++w) { L += sl[w]; C += sc[w]; }
        out[0] = L / fmaxf(C, 1.0f);
    }
}

// ---------------------------------------------------------------------------
// Inputs (metadata order): inputs f32 [N,1000], target i32 [N],
//                          onehot_num, onehot_den, weights (unused)
// ---------------------------------------------------------------------------
extern "C" void kernel_launch(void* const* d_in, const int* in_sizes, int n_in,
                              void* d_out, int out_size)
{
    const float* inputs = (const float*)d_in[0];
    const int*   target = (const int*)d_in[1];
    float*       out    = (float*)d_out;

    const int N = in_sizes[1];

    hll_main <<<NBLK, 256>>>(inputs, target, N);
    hll_final<<<1,    256>>>(out);
}

// round 7
// speedup vs baseline: 1.0746x; 1.0746x over previous
#include <cuda_runtime.h>
#include <cuda_bf16.h>

#define NCLS   1000
#define NCLS4  250          // NCLS / 4 float4 per row
#define NBLK   592          // 148 SMs x 4 resident blocks (256 thr)
#define NWARPS (NBLK * 8)   // total persistent warps

// Scratch (no device allocation allowed -> __device__ globals)
__device__ float2       g_part[NBLK];   // per-block (sum_loss, sum_valid)
__device__ unsigned int g_ctr = 0;      // last-block ticket counter

// ---------------------------------------------------------------------------
// Single fused kernel: persistent warp-per-token main pass + per-block combine
// + last-block final reduction (deterministic: fixed summation order).
// ---------------------------------------------------------------------------
__global__ __launch_bounds__(256) void hll_fused(
    const float* __restrict__ inputs,
    const int*   __restrict__ target,   // int32 (JAX downcasts int64 w/o x64)
    float* __restrict__ out,
    int N)
{
    const int warp  = threadIdx.x >> 5;
    const int lane  = threadIdx.x & 31;
    const int gwarp = (blockIdx.x << 3) + warp;

    float lsum = 0.f, csum = 0.f;       // lane-0 accumulators

    for (int n = gwarp; n < N; n += NWARPS) {
        const int ti = target[n];
        const bool valid = (ti != -100);
        const int t   = valid ? ti : 0;
        const int lo1 = (t / 10)  * 10;    // start of 10-block
        const int lo2 = (t / 100) * 100;   // start of 100-block

        const float*  __restrict__ rowf = inputs + (size_t)n * NCLS;
        const float4* __restrict__ row  = reinterpret_cast<const float4*>(rowf);

        // ---- Streaming pass: full row sum, compare-free ----
        float a0 = 0.f, a1 = 0.f, a2 = 0.f, a3 = 0.f;
        #pragma unroll
        for (int it = 0; it < 8; ++it) {
            const int idx = lane + (it << 5);
            if (idx < NCLS4) {
                const float4 v = row[idx];
                a0 += v.x; a1 += v.y; a2 += v.z; a3 += v.w;
            }
        }
        float s3 = (a0 + a1) + (a2 + a3);

        // ---- Targeted re-reads (L1 hits) ----
        float s2 = 0.f, s1 = 0.f;
        if (lane < 25) {                       // 100 floats = 25 float4
            const float4 v = row[(lo2 >> 2) + lane];
            s2 = (v.x + v.y) + (v.z + v.w);
        }
        if (lane < 10) s1 = rowf[lo1 + lane];  // 10 floats
        const float s0 = rowf[t];              // broadcast read (L1 hit)

        // ---- Warp butterfly reduce s1,s2,s3 ----
        #pragma unroll
        for (int off = 16; off; off >>= 1) {
            s1 += __shfl_xor_sync(0xffffffffu, s1, off);
            s2 += __shfl_xor_sync(0xffffffffu, s2, off);
            s3 += __shfl_xor_sync(0xffffffffu, s3, off);
        }

        if (lane == 0 && valid) {
            const float t0 = (s0 != 0.f) ? -logf(s0 / s1) : 0.f;
            const float t1 = (s1 != 0.f) ? -logf(s1 / s2) : 0.f;
            const float t2 = (s2 != 0.f) ? -logf(s2 / s3) : 0.f;
            lsum += t0 + 0.60653065971263342f * t1   // exp(-0.5)
                       + 0.36787944117144233f * t2;  // exp(-1.0)
            csum += 1.f;
        }
    }

    // ---- Per-block combine of the 8 warp accumulators ----
    __shared__ float2 sacc[8];
    __shared__ bool   s_last;
    if (lane == 0) sacc[warp] = make_float2(lsum, csum);
    __syncthreads();
    if (threadIdx.x == 0) {
        float L = 0.f, C = 0.f;
        #pragma unroll
        for (int w = 0; w < 8; ++w) { L += sacc[w].x; C += sacc[w].y; }
        g_part[blockIdx.x] = make_float2(L, C);
        __threadfence();
        const unsigned int ticket = atomicAdd(&g_ctr, 1u);
        s_last = (ticket == NBLK - 1);
    }
    __syncthreads();

    // ---- Last block: reduce the 592 L2-resident partials ----
    if (s_last) {
        float l = 0.f, c = 0.f;
        for (int i = threadIdx.x; i < NBLK; i += 256) {
            const float2 v = g_part[i];
            l += v.x;
            c += v.y;
        }
        #pragma unroll
        for (int off = 16; off; off >>= 1) {
            l += __shfl_xor_sync(0xffffffffu, l, off);
            c += __shfl_xor_sync(0xffffffffu, c, off);
        }
        __shared__ float sl[8], sc[8];
        if (lane == 0) { sl[warp] = l; sc[warp] = c; }
        __syncthreads();
        if (threadIdx.x == 0) {
            float L = 0.f, C = 0.f;
            #pragma unroll
            for (int w = 0; w < 8; ++w) { L += sl[w]; C += sc[w]; }
            out[0] = L / fmaxf(C, 1.0f);
            g_ctr = 0;   // reset for next graph replay (deterministic)
        }
    }
}

// ---------------------------------------------------------------------------
// Inputs (metadata order): inputs f32 [N,1000], target i32 [N],
//                          onehot_num, onehot_den, weights (unused)
// ---------------------------------------------------------------------------
extern "C" void kernel_launch(void* const* d_in, const int* in_sizes, int n_in,
                              void* d_out, int out_size)
{
    const float* inputs = (const float*)d_in[0];
    const int*   target = (const int*)d_in[1];
    float*       out    = (float*)d_out;

    const int N = in_sizes[1];

    hll_fused<<<NBLK, 256>>>(inputs, target, out, N);
}